// round 6
// baseline (speedup 1.0000x reference)
#include <cuda_runtime.h>
#include <cstdint>

#define NB 2
#define NH 12
#define SQ 2048
#define DH 64
#define DM 768
#define SCALE 0.125f

// Scratch for Q/K/V in [B, H, S, Dh] layout (device globals: allocation-free rule)
__device__ float g_q[NB * NH * SQ * DH];
__device__ float g_k[NB * NH * SQ * DH];
__device__ float g_v[NB * NH * SQ * DH];

__device__ __forceinline__ uint32_t f2tf(float f) {
    uint32_t u;
    asm("cvt.rna.tf32.f32 %0, %1;" : "=r"(u) : "f"(f));
    return u;
}

__device__ __forceinline__ uint4 cvt4(float4 v) {
    return make_uint4(f2tf(v.x), f2tf(v.y), f2tf(v.z), f2tf(v.w));
}

__device__ __forceinline__ void mma8(float* c, const uint32_t* a, const uint32_t* b) {
    asm volatile(
        "mma.sync.aligned.m16n8k8.row.col.f32.tf32.tf32.f32 "
        "{%0,%1,%2,%3}, {%4,%5,%6,%7}, {%8,%9}, {%0,%1,%2,%3};\n"
        : "+f"(c[0]), "+f"(c[1]), "+f"(c[2]), "+f"(c[3])
        : "r"(a[0]), "r"(a[1]), "r"(a[2]), "r"(a[3]), "r"(b[0]), "r"(b[1]));
}

__device__ __forceinline__ void cpasync16(uint32_t dst, const void* src) {
    asm volatile("cp.async.ca.shared.global [%0], [%1], 16;\n" :: "r"(dst), "l"(src));
}

// ---------------------------------------------------------------------------
// Kernel 1: fused QKV projection.  out[m,n] = X[m,:].W[n,:]+b[n]
// M=4096, N=768, K=768.  BM=128, BN=128, BK=32. 8 warps (4x2), warp 32x64.
// ---------------------------------------------------------------------------
__global__ __launch_bounds__(256, 2) void qkv_kernel(
    const float* __restrict__ X,
    const float* __restrict__ Wq, const float* __restrict__ bq,
    const float* __restrict__ Wk, const float* __restrict__ bk,
    const float* __restrict__ Wv, const float* __restrict__ bv)
{
    const float* W;
    const float* bias;
    float* out;
    if (blockIdx.z == 0)      { W = Wq; bias = bq; out = g_q; }
    else if (blockIdx.z == 1) { W = Wk; bias = bk; out = g_k; }
    else                      { W = Wv; bias = bv; out = g_v; }

    __shared__ uint32_t As[128][36];
    __shared__ uint32_t Bs[128][36];

    const int tid  = threadIdx.x;
    const int lane = tid & 31;
    const int warp = tid >> 5;
    const int wm   = warp >> 1;   // 0..3: 32 rows
    const int wn   = warp & 1;    // 0..1: 64 cols
    const int m0   = blockIdx.y * 128;
    const int n0   = blockIdx.x * 128;

    float acc[2][8][4];
    #pragma unroll
    for (int i = 0; i < 2; i++)
        #pragma unroll
        for (int j = 0; j < 8; j++)
            #pragma unroll
            for (int e = 0; e < 4; e++) acc[i][j][e] = 0.f;

    const int ar = tid >> 3;
    const int ac = (tid & 7) * 4;

    for (int kt = 0; kt < DM / 32; kt++) {
        const int k0 = kt * 32;
        #pragma unroll
        for (int it = 0; it < 4; it++) {
            int r = ar + it * 32;
            float4 v = *(const float4*)&X[(size_t)(m0 + r) * DM + k0 + ac];
            *(uint4*)&As[r][ac] = cvt4(v);
            float4 w = *(const float4*)&W[(size_t)(n0 + r) * DM + k0 + ac];
            *(uint4*)&Bs[r][ac] = cvt4(w);
        }
        __syncthreads();
        #pragma unroll
        for (int kk = 0; kk < 4; kk++) {
            uint32_t a[2][4], b[8][2];
            #pragma unroll
            for (int i = 0; i < 2; i++) {
                int r = wm * 32 + i * 16 + (lane >> 2);
                int c = kk * 8 + (lane & 3);
                a[i][0] = As[r][c];
                a[i][1] = As[r + 8][c];
                a[i][2] = As[r][c + 4];
                a[i][3] = As[r + 8][c + 4];
            }
            #pragma unroll
            for (int j = 0; j < 8; j++) {
                int cc = wn * 64 + j * 8 + (lane >> 2);
                int c  = kk * 8 + (lane & 3);
                b[j][0] = Bs[cc][c];
                b[j][1] = Bs[cc][c + 4];
            }
            #pragma unroll
            for (int i = 0; i < 2; i++)
                #pragma unroll
                for (int j = 0; j < 8; j++)
                    mma8(acc[i][j], a[i], b[j]);
        }
        __syncthreads();
    }

    #pragma unroll
    for (int i = 0; i < 2; i++) {
        #pragma unroll
        for (int j = 0; j < 8; j++) {
            int n  = n0 + wn * 64 + j * 8 + 2 * (lane & 3);
            int h  = n >> 6;
            int dh = n & 63;
            float b0 = bias[n], b1 = bias[n + 1];
            #pragma unroll
            for (int rr = 0; rr < 2; rr++) {
                int m  = m0 + wm * 32 + i * 16 + (lane >> 2) + rr * 8;
                int bb = m >> 11;
                int s  = m & 2047;
                size_t idx = (((size_t)(bb * NH + h)) * SQ + s) * DH + dh;
                out[idx]     = acc[i][j][rr * 2 + 0] + b0;
                out[idx + 1] = acc[i][j][rr * 2 + 1] + b1;
            }
        }
    }
}

// ---------------------------------------------------------------------------
// Kernel 2: flash-style attention with RealFormer residual.
// Grid: (S/128, H, B). 8 warps; warp w owns q rows [128*bx + 16w, +16).
// cp.async double-buffered RAW f32 staging (chunk j+1 copied behind chunk j's
// compute), then a bank-conflict-free smem convert pass (rna preserved).
// V stored pair-interleaved sVp[key/2][dh][2] (stride 136 = 8 mod 32):
// PV B-frags are LDS.64, conflict-free; converter writes STS.128 conflict-free.
// PV A-frags direct from QK C registers (shared k-permutation).
// ---------------------------------------------------------------------------
#define SK_ROW 72
#define SVP_STRIDE 136
#define RAW_WORDS (2 * 2048)            // [2 bufs][2048 floats] per tensor
#define ATTN_SMEM ((4 * 2048 + 32 * SK_ROW + 16 * SVP_STRIDE) * 4)

__global__ __launch_bounds__(256, 2) void attn_kernel(
    const float* __restrict__ res_in,
    const float* __restrict__ mask,
    float* __restrict__ ctx_out,
    float* __restrict__ res_out)
{
    extern __shared__ uint32_t dyn[];
    float* rawK = (float*)dyn;                       // [2][2048]
    float* rawV = (float*)(dyn + RAW_WORDS);         // [2][2048]
    uint32_t* sK  = dyn + 2 * RAW_WORDS;             // [32][72]
    uint32_t* sVp = sK + 32 * SK_ROW;                // [16][136]

    const int tid  = threadIdx.x;
    const int lane = tid & 31;
    const int warp = tid >> 5;
    const int q4   = lane & 3;
    const int r4   = lane >> 2;
    const int h  = blockIdx.y;
    const int b  = blockIdx.z;
    const int bh = b * NH + h;
    const int q0 = blockIdx.x * 128;

    const float* Q = g_q + (size_t)bh * SQ * DH;
    const float* K = g_k + (size_t)bh * SQ * DH;
    const float* V = g_v + (size_t)bh * SQ * DH;

    const uint32_t rawK_s = (uint32_t)__cvta_generic_to_shared(rawK);
    const uint32_t rawV_s = (uint32_t)__cvta_generic_to_shared(rawV);

    // Q fragments, permuted k within groups of 8 (lane q -> cols 2q, 2q+1)
    uint32_t qf[8][4];
    {
        int r0 = q0 + warp * 16 + r4;
        const float* Qr0 = Q + (size_t)r0 * DH;
        const float* Qr8 = Qr0 + 8 * DH;
        #pragma unroll
        for (int kk = 0; kk < 8; kk++) {
            int c = kk * 8 + 2 * q4;
            qf[kk][0] = f2tf(Qr0[c]);
            qf[kk][1] = f2tf(Qr8[c]);
            qf[kk][2] = f2tf(Qr0[c + 1]);
            qf[kk][3] = f2tf(Qr8[c + 1]);
        }
    }

    float Oacc[8][4];
    #pragma unroll
    for (int f = 0; f < 8; f++)
        #pragma unroll
        for (int e = 0; e < 4; e++) Oacc[f][e] = 0.f;
    float mrow0 = -1e30f, mrow1 = -1e30f;
    float lrow0 = 0.f, lrow1 = 0.f;

    const int rq0 = q0 + warp * 16 + r4;
    const size_t res0 = ((size_t)bh * SQ + rq0) * SQ;
    const size_t res8 = res0 + (size_t)8 * SQ;
    const float* mrk = mask + b * SQ;

    // prologue: async-copy chunk 0 (raw f32, no registers)
    {
        const float* Ks = K;
        const float* Vs = V;
        cpasync16(rawK_s + (uint32_t)(tid * 16),        Ks + tid * 4);
        cpasync16(rawK_s + (uint32_t)(4096 + tid * 16), Ks + 1024 + tid * 4);
        cpasync16(rawV_s + (uint32_t)(tid * 16),        Vs + tid * 4);
        cpasync16(rawV_s + (uint32_t)(4096 + tid * 16), Vs + 1024 + tid * 4);
        asm volatile("cp.async.commit_group;" ::: "memory");
    }

    const int vp = tid >> 4;        // 0..15 : key pair
    const int vt = tid & 15;        // dh/2 index

    for (int j = 0; j < SQ / 32; j++) {
        const int kb = j * 32;
        const int buf = j & 1;

        asm volatile("cp.async.wait_group 0;" ::: "memory");
        __syncthreads();   // raw[buf] visible; prev chunk's sK/sVp reads done

        // issue chunk j+1 copy (runs behind this whole chunk's work)
        if (j < SQ / 32 - 1) {
            const float* Ks = K + (size_t)(j + 1) * 2048;
            const float* Vs = V + (size_t)(j + 1) * 2048;
            uint32_t ko = rawK_s + (uint32_t)((buf ^ 1) * 8192);
            uint32_t vo = rawV_s + (uint32_t)((buf ^ 1) * 8192);
            cpasync16(ko + (uint32_t)(tid * 16),        Ks + tid * 4);
            cpasync16(ko + (uint32_t)(4096 + tid * 16), Ks + 1024 + tid * 4);
            cpasync16(vo + (uint32_t)(tid * 16),        Vs + tid * 4);
            cpasync16(vo + (uint32_t)(4096 + tid * 16), Vs + 1024 + tid * 4);
            asm volatile("cp.async.commit_group;" ::: "memory");
        }

        // convert pass: raw f32 -> tf32 tiles (all smem, conflict-free)
        const float* rK = rawK + buf * 2048;
        const float* rV = rawV + buf * 2048;
        #pragma unroll
        for (int it = 0; it < 2; it++) {
            int idx = tid + it * 256;
            float4 kv = *(const float4*)&rK[idx * 4];
            int key = idx >> 4, lcc = (idx & 15) * 4;
            *(uint4*)&sK[key * SK_ROW + lcc] = cvt4(kv);
        }
        #pragma unroll
        for (int it = 0; it < 2; it++) {
            int dd = 2 * vt + 32 * it;
            float2 v0 = *(const float2*)&rV[(2 * vp) * 64 + dd];
            float2 v1 = *(const float2*)&rV[(2 * vp + 1) * 64 + dd];
            *(uint4*)&sVp[vp * SVP_STRIDE + 2 * dd] =
                make_uint4(f2tf(v0.x), f2tf(v1.x), f2tf(v0.y), f2tf(v1.y));
        }
        __syncthreads();

        // residual loads (streaming; latency overlaps QK mma)
        float2 rin0[4], rin8[4];
        #pragma unroll
        for (int f = 0; f < 4; f++) {
            int col = kb + f * 8 + 2 * q4;
            rin0[f] = __ldcs((const float2*)&res_in[res0 + col]);
            rin8[f] = __ldcs((const float2*)&res_in[res8 + col]);
        }

        // S = Q . K^T  (m16 x n32, k=64), B pairs contiguous -> LDS.64
        float s[4][4];
        #pragma unroll
        for (int f = 0; f < 4; f++)
            #pragma unroll
            for (int e = 0; e < 4; e++) s[f][e] = 0.f;
        #pragma unroll
        for (int kk = 0; kk < 8; kk++) {
            const int c = kk * 8 + 2 * q4;
            #pragma unroll
            for (int f = 0; f < 4; f++) {
                int key = f * 8 + r4;
                uint2 bp = *(const uint2*)&sK[key * SK_ROW + c];
                uint32_t b2[2] = {bp.x, bp.y};
                mma8(s[f], qf[kk], b2);
            }
        }

        // scale + residual, write scores_res_out pre-mask, then +mask
        #pragma unroll
        for (int f = 0; f < 4; f++) {
            int col = kb + f * 8 + 2 * q4;
            s[f][0] = s[f][0] * SCALE + rin0[f].x;
            s[f][1] = s[f][1] * SCALE + rin0[f].y;
            s[f][2] = s[f][2] * SCALE + rin8[f].x;
            s[f][3] = s[f][3] * SCALE + rin8[f].y;
            __stcs((float2*)&res_out[res0 + col], make_float2(s[f][0], s[f][1]));
            __stcs((float2*)&res_out[res8 + col], make_float2(s[f][2], s[f][3]));
            float2 mk = *(const float2*)&mrk[col];
            s[f][0] += mk.x; s[f][1] += mk.y;
            s[f][2] += mk.x; s[f][3] += mk.y;
        }

        // online softmax (rows within a quad: shfl xor 1,2)
        float cmax0 = -1e30f, cmax1 = -1e30f;
        #pragma unroll
        for (int f = 0; f < 4; f++) {
            cmax0 = fmaxf(cmax0, fmaxf(s[f][0], s[f][1]));
            cmax1 = fmaxf(cmax1, fmaxf(s[f][2], s[f][3]));
        }
        cmax0 = fmaxf(cmax0, __shfl_xor_sync(0xffffffff, cmax0, 1));
        cmax0 = fmaxf(cmax0, __shfl_xor_sync(0xffffffff, cmax0, 2));
        cmax1 = fmaxf(cmax1, __shfl_xor_sync(0xffffffff, cmax1, 1));
        cmax1 = fmaxf(cmax1, __shfl_xor_sync(0xffffffff, cmax1, 2));
        float nm0 = fmaxf(mrow0, cmax0);
        float nm1 = fmaxf(mrow1, cmax1);
        float corr0 = __expf(mrow0 - nm0);
        float corr1 = __expf(mrow1 - nm1);
        mrow0 = nm0; mrow1 = nm1;

        float sum0 = 0.f, sum1 = 0.f;
        #pragma unroll
        for (int f = 0; f < 4; f++) {
            s[f][0] = __expf(s[f][0] - nm0);
            s[f][1] = __expf(s[f][1] - nm0);
            s[f][2] = __expf(s[f][2] - nm1);
            s[f][3] = __expf(s[f][3] - nm1);
            sum0 += s[f][0] + s[f][1];
            sum1 += s[f][2] + s[f][3];
        }
        sum0 += __shfl_xor_sync(0xffffffff, sum0, 1);
        sum0 += __shfl_xor_sync(0xffffffff, sum0, 2);
        sum1 += __shfl_xor_sync(0xffffffff, sum1, 1);
        sum1 += __shfl_xor_sync(0xffffffff, sum1, 2);
        lrow0 = lrow0 * corr0 + sum0;
        lrow1 = lrow1 * corr1 + sum1;
        #pragma unroll
        for (int f = 0; f < 8; f++) {
            Oacc[f][0] *= corr0; Oacc[f][1] *= corr0;
            Oacc[f][2] *= corr1; Oacc[f][3] *= corr1;
        }

        // O += P . V : A-frags direct from QK C regs; B-frags LDS.64 from sVp
        #pragma unroll
        for (int kk = 0; kk < 4; kk++) {
            uint32_t a[4] = { f2tf(s[kk][0]), f2tf(s[kk][2]),
                              f2tf(s[kk][1]), f2tf(s[kk][3]) };
            const int pr = 4 * kk + q4;   // key pair index (kr>>1)
            #pragma unroll
            for (int f = 0; f < 8; f++) {
                int nc = f * 8 + r4;
                uint2 bp = *(const uint2*)&sVp[pr * SVP_STRIDE + nc * 2];
                uint32_t b2[2] = {bp.x, bp.y};
                mma8(Oacc[f], a, b2);
            }
        }
    }

    // Epilogue: O / l, store ctx [B, S, H*Dh]
    float inv0 = 1.f / lrow0;
    float inv1 = 1.f / lrow1;
    int row0 = q0 + warp * 16 + r4;
    #pragma unroll
    for (int f = 0; f < 8; f++) {
        int dh = f * 8 + 2 * q4;
        size_t i0 = ((size_t)b * SQ + row0) * DM + h * DH + dh;
        size_t i8 = ((size_t)b * SQ + row0 + 8) * DM + h * DH + dh;
        *(float2*)&ctx_out[i0] = make_float2(Oacc[f][0] * inv0, Oacc[f][1] * inv0);
        *(float2*)&ctx_out[i8] = make_float2(Oacc[f][2] * inv1, Oacc[f][3] * inv1);
    }
}

extern "C" void kernel_launch(void* const* d_in, const int* in_sizes, int n_in,
                              void* d_out, int out_size) {
    const float* X    = (const float*)d_in[0];
    const float* mask = (const float*)d_in[1];
    const float* res  = (const float*)d_in[2];
    const float* Wq   = (const float*)d_in[3];
    const float* bq   = (const float*)d_in[4];
    const float* Wk   = (const float*)d_in[5];
    const float* bk   = (const float*)d_in[6];
    const float* Wv   = (const float*)d_in[7];
    const float* bv   = (const float*)d_in[8];

    float* ctx     = (float*)d_out;
    float* res_out = (float*)d_out + (size_t)NB * SQ * DM;

    cudaFuncSetAttribute(attn_kernel, cudaFuncAttributeMaxDynamicSharedMemorySize, ATTN_SMEM);

    dim3 g1(DM / 128, (NB * SQ) / 128, 3);
    qkv_kernel<<<g1, 256>>>(X, Wq, bq, Wk, bk, Wv, bv);

    dim3 g2(SQ / 128, NH, NB);
    attn_kernel<<<g2, 256, ATTN_SMEM>>>(res, mask, ctx, res_out);
}

// round 7
// speedup vs baseline: 1.6861x; 1.6861x over previous
#include <cuda_runtime.h>
#include <cstdint>

#define NB 2
#define NH 12
#define SQ 2048
#define DH 64
#define DM 768
#define SCALE 0.125f

// Scratch for Q/K/V in [B, H, S, Dh] layout (device globals: allocation-free rule)
__device__ float g_q[NB * NH * SQ * DH];
__device__ float g_k[NB * NH * SQ * DH];
__device__ float g_v[NB * NH * SQ * DH];

__device__ __forceinline__ uint32_t f2tf(float f) {
    uint32_t u;
    asm("cvt.rna.tf32.f32 %0, %1;" : "=r"(u) : "f"(f));
    return u;
}

__device__ __forceinline__ uint4 cvt4(float4 v) {
    return make_uint4(f2tf(v.x), f2tf(v.y), f2tf(v.z), f2tf(v.w));
}

__device__ __forceinline__ void mma8(float* c, const uint32_t* a, const uint32_t* b) {
    asm volatile(
        "mma.sync.aligned.m16n8k8.row.col.f32.tf32.tf32.f32 "
        "{%0,%1,%2,%3}, {%4,%5,%6,%7}, {%8,%9}, {%0,%1,%2,%3};\n"
        : "+f"(c[0]), "+f"(c[1]), "+f"(c[2]), "+f"(c[3])
        : "r"(a[0]), "r"(a[1]), "r"(a[2]), "r"(a[3]), "r"(b[0]), "r"(b[1]));
}

// ---------------------------------------------------------------------------
// Kernel 1: fused QKV projection (R5/R3 version).  out[m,n] = X[m,:].W[n,:]+b
// M=4096, N=768, K=768.  BM=128, BN=64, BK=32. 8 warps (4x2), warp 32x32.
// ---------------------------------------------------------------------------
__global__ __launch_bounds__(256) void qkv_kernel(
    const float* __restrict__ X,
    const float* __restrict__ Wq, const float* __restrict__ bq,
    const float* __restrict__ Wk, const float* __restrict__ bk,
    const float* __restrict__ Wv, const float* __restrict__ bv)
{
    const float* W;
    const float* bias;
    float* out;
    if (blockIdx.z == 0)      { W = Wq; bias = bq; out = g_q; }
    else if (blockIdx.z == 1) { W = Wk; bias = bk; out = g_k; }
    else                      { W = Wv; bias = bv; out = g_v; }

    __shared__ uint32_t As[128][36];
    __shared__ uint32_t Bs[64][36];

    const int tid  = threadIdx.x;
    const int lane = tid & 31;
    const int warp = tid >> 5;
    const int wm   = warp >> 1;
    const int wn   = warp & 1;
    const int m0   = blockIdx.y * 128;
    const int n0   = blockIdx.x * 64;

    float acc[2][4][4];
    #pragma unroll
    for (int i = 0; i < 2; i++)
        #pragma unroll
        for (int j = 0; j < 4; j++)
            #pragma unroll
            for (int e = 0; e < 4; e++) acc[i][j][e] = 0.f;

    const int ar = tid >> 3;
    const int ac = (tid & 7) * 4;

    for (int kt = 0; kt < DM / 32; kt++) {
        const int k0 = kt * 32;
        #pragma unroll
        for (int it = 0; it < 4; it++) {
            int r = ar + it * 32;
            float4 v = *(const float4*)&X[(size_t)(m0 + r) * DM + k0 + ac];
            *(uint4*)&As[r][ac] = cvt4(v);
        }
        #pragma unroll
        for (int it = 0; it < 2; it++) {
            int r = ar + it * 32;
            float4 v = *(const float4*)&W[(size_t)(n0 + r) * DM + k0 + ac];
            *(uint4*)&Bs[r][ac] = cvt4(v);
        }
        __syncthreads();
        #pragma unroll
        for (int kk = 0; kk < 4; kk++) {
            uint32_t a[2][4], b[4][2];
            #pragma unroll
            for (int i = 0; i < 2; i++) {
                int r = wm * 32 + i * 16 + (lane >> 2);
                int c = kk * 8 + (lane & 3);
                a[i][0] = As[r][c];
                a[i][1] = As[r + 8][c];
                a[i][2] = As[r][c + 4];
                a[i][3] = As[r + 8][c + 4];
            }
            #pragma unroll
            for (int j = 0; j < 4; j++) {
                int cc = wn * 32 + j * 8 + (lane >> 2);
                int c  = kk * 8 + (lane & 3);
                b[j][0] = Bs[cc][c];
                b[j][1] = Bs[cc][c + 4];
            }
            #pragma unroll
            for (int i = 0; i < 2; i++)
                #pragma unroll
                for (int j = 0; j < 4; j++)
                    mma8(acc[i][j], a[i], b[j]);
        }
        __syncthreads();
    }

    #pragma unroll
    for (int i = 0; i < 2; i++) {
        #pragma unroll
        for (int j = 0; j < 4; j++) {
            int n  = n0 + wn * 32 + j * 8 + 2 * (lane & 3);
            int h  = n >> 6;
            int dh = n & 63;
            float b0 = bias[n], b1 = bias[n + 1];
            #pragma unroll
            for (int rr = 0; rr < 2; rr++) {
                int m  = m0 + wm * 32 + i * 16 + (lane >> 2) + rr * 8;
                int bb = m >> 11;
                int s  = m & 2047;
                size_t idx = (((size_t)(bb * NH + h)) * SQ + s) * DH + dh;
                out[idx]     = acc[i][j][rr * 2 + 0] + b0;
                out[idx + 1] = acc[i][j][rr * 2 + 1] + b1;
            }
        }
    }
}

// ---------------------------------------------------------------------------
// Kernel 2: flash-style attention with RealFormer residual (R5 structure).
// CHANGE vs R5: CTA = 128 threads / 64 q-rows (4 warps x 16 rows), 4 CTAs/SM
// -> 4 independent barrier domains per SM for latency hiding.
// Grid: (S/64, H, B). Per-warp code identical to R5:
//  - QK B-frags LDS.64 from sK (stride 72, conflict-free per 16-lane phase)
//  - PV A-frags direct from QK C registers (shared k-permutation)
//  - residual loads hoisted to chunk top, streaming ld/st.
// ---------------------------------------------------------------------------
#define SK_ROW 72
#define SV_ROW 68

__global__ __launch_bounds__(128, 4) void attn_kernel(
    const float* __restrict__ res_in,
    const float* __restrict__ mask,
    float* __restrict__ ctx_out,
    float* __restrict__ res_out)
{
    __shared__ uint32_t sK[32 * SK_ROW];
    __shared__ uint32_t sV[32 * SV_ROW];

    const int tid  = threadIdx.x;
    const int lane = tid & 31;
    const int warp = tid >> 5;          // 0..3
    const int q4   = lane & 3;
    const int r4   = lane >> 2;
    const int h  = blockIdx.y;
    const int b  = blockIdx.z;
    const int bh = b * NH + h;
    const int q0 = blockIdx.x * 64;

    const float* Q = g_q + (size_t)bh * SQ * DH;
    const float* K = g_k + (size_t)bh * SQ * DH;
    const float* V = g_v + (size_t)bh * SQ * DH;

    // Q fragments, permuted k within groups of 8 (lane q -> cols 2q, 2q+1)
    uint32_t qf[8][4];
    {
        int r0 = q0 + warp * 16 + r4;
        const float* Qr0 = Q + (size_t)r0 * DH;
        const float* Qr8 = Qr0 + 8 * DH;
        #pragma unroll
        for (int kk = 0; kk < 8; kk++) {
            int c = kk * 8 + 2 * q4;
            qf[kk][0] = f2tf(Qr0[c]);
            qf[kk][1] = f2tf(Qr8[c]);
            qf[kk][2] = f2tf(Qr0[c + 1]);
            qf[kk][3] = f2tf(Qr8[c + 1]);
        }
    }

    float Oacc[8][4];
    #pragma unroll
    for (int f = 0; f < 8; f++)
        #pragma unroll
        for (int e = 0; e < 4; e++) Oacc[f][e] = 0.f;
    float mrow0 = -1e30f, mrow1 = -1e30f;
    float lrow0 = 0.f, lrow1 = 0.f;

    const int rq0 = q0 + warp * 16 + r4;
    const size_t res0 = ((size_t)bh * SQ + rq0) * SQ;
    const size_t res8 = res0 + (size_t)8 * SQ;
    const float* mrk = mask + b * SQ;

    const int lr = tid >> 4;          // 0..7
    const int lc = (tid & 15) * 4;    // 0..60

    for (int j = 0; j < SQ / 32; j++) {
        const int kb = j * 32;
        __syncthreads();   // previous chunk's reads of sK/sV done

        // Residual loads for THIS chunk (independent of smem; overlap fill+QK)
        float2 rin0[4], rin8[4];
        #pragma unroll
        for (int f = 0; f < 4; f++) {
            int col = kb + f * 8 + 2 * q4;
            rin0[f] = __ldcs((const float2*)&res_in[res0 + col]);
            rin8[f] = __ldcs((const float2*)&res_in[res8 + col]);
        }

        // Load K,V chunk (32 keys x 64 dh), coalesced float4, 128 threads
        {
            #pragma unroll
            for (int it = 0; it < 4; it++) {
                int key = lr + it * 8;
                float4 kv = *(const float4*)&K[(size_t)(kb + key) * DH + lc];
                *(uint4*)&sK[key * SK_ROW + lc] = cvt4(kv);
                float4 vv = *(const float4*)&V[(size_t)(kb + key) * DH + lc];
                *(uint4*)&sV[key * SV_ROW + lc] = cvt4(vv);
            }
        }
        __syncthreads();

        // S = Q . K^T  (m16 x n32, k=64), B pairs contiguous -> LDS.64
        float s[4][4];
        #pragma unroll
        for (int f = 0; f < 4; f++)
            #pragma unroll
            for (int e = 0; e < 4; e++) s[f][e] = 0.f;
        #pragma unroll
        for (int kk = 0; kk < 8; kk++) {
            const int c = kk * 8 + 2 * q4;
            #pragma unroll
            for (int f = 0; f < 4; f++) {
                int key = f * 8 + r4;
                uint2 bp = *(const uint2*)&sK[key * SK_ROW + c];
                uint32_t b2[2] = {bp.x, bp.y};
                mma8(s[f], qf[kk], b2);
            }
        }

        // scale + residual, write scores_res_out pre-mask, then +mask
        #pragma unroll
        for (int f = 0; f < 4; f++) {
            int col = kb + f * 8 + 2 * q4;
            s[f][0] = s[f][0] * SCALE + rin0[f].x;
            s[f][1] = s[f][1] * SCALE + rin0[f].y;
            s[f][2] = s[f][2] * SCALE + rin8[f].x;
            s[f][3] = s[f][3] * SCALE + rin8[f].y;
            __stcs((float2*)&res_out[res0 + col], make_float2(s[f][0], s[f][1]));
            __stcs((float2*)&res_out[res8 + col], make_float2(s[f][2], s[f][3]));
            float2 mk = *(const float2*)&mrk[col];
            s[f][0] += mk.x; s[f][1] += mk.y;
            s[f][2] += mk.x; s[f][3] += mk.y;
        }

        // online softmax (rows within a quad: shfl xor 1,2)
        float cmax0 = -1e30f, cmax1 = -1e30f;
        #pragma unroll
        for (int f = 0; f < 4; f++) {
            cmax0 = fmaxf(cmax0, fmaxf(s[f][0], s[f][1]));
            cmax1 = fmaxf(cmax1, fmaxf(s[f][2], s[f][3]));
        }
        cmax0 = fmaxf(cmax0, __shfl_xor_sync(0xffffffff, cmax0, 1));
        cmax0 = fmaxf(cmax0, __shfl_xor_sync(0xffffffff, cmax0, 2));
        cmax1 = fmaxf(cmax1, __shfl_xor_sync(0xffffffff, cmax1, 1));
        cmax1 = fmaxf(cmax1, __shfl_xor_sync(0xffffffff, cmax1, 2));
        float nm0 = fmaxf(mrow0, cmax0);
        float nm1 = fmaxf(mrow1, cmax1);
        float corr0 = __expf(mrow0 - nm0);
        float corr1 = __expf(mrow1 - nm1);
        mrow0 = nm0; mrow1 = nm1;

        float sum0 = 0.f, sum1 = 0.f;
        #pragma unroll
        for (int f = 0; f < 4; f++) {
            s[f][0] = __expf(s[f][0] - nm0);
            s[f][1] = __expf(s[f][1] - nm0);
            s[f][2] = __expf(s[f][2] - nm1);
            s[f][3] = __expf(s[f][3] - nm1);
            sum0 += s[f][0] + s[f][1];
            sum1 += s[f][2] + s[f][3];
        }
        sum0 += __shfl_xor_sync(0xffffffff, sum0, 1);
        sum0 += __shfl_xor_sync(0xffffffff, sum0, 2);
        sum1 += __shfl_xor_sync(0xffffffff, sum1, 1);
        sum1 += __shfl_xor_sync(0xffffffff, sum1, 2);
        lrow0 = lrow0 * corr0 + sum0;
        lrow1 = lrow1 * corr1 + sum1;
        #pragma unroll
        for (int f = 0; f < 8; f++) {
            Oacc[f][0] *= corr0; Oacc[f][1] *= corr0;
            Oacc[f][2] *= corr1; Oacc[f][3] *= corr1;
        }

        // O += P . V : A-fragments DIRECT from QK C registers.
        #pragma unroll
        for (int kk = 0; kk < 4; kk++) {
            uint32_t a[4] = { f2tf(s[kk][0]), f2tf(s[kk][2]),
                              f2tf(s[kk][1]), f2tf(s[kk][3]) };
            const int kr = kk * 8 + 2 * q4;
            #pragma unroll
            for (int f = 0; f < 8; f++) {
                int nc = f * 8 + r4;
                uint32_t b2[2] = { sV[kr * SV_ROW + nc], sV[(kr + 1) * SV_ROW + nc] };
                mma8(Oacc[f], a, b2);
            }
        }
    }

    // Epilogue: O / l, store ctx [B, S, H*Dh]
    float inv0 = 1.f / lrow0;
    float inv1 = 1.f / lrow1;
    int row0 = q0 + warp * 16 + r4;
    #pragma unroll
    for (int f = 0; f < 8; f++) {
        int dh = f * 8 + 2 * q4;
        size_t i0 = ((size_t)b * SQ + row0) * DM + h * DH + dh;
        size_t i8 = ((size_t)b * SQ + row0 + 8) * DM + h * DH + dh;
        *(float2*)&ctx_out[i0] = make_float2(Oacc[f][0] * inv0, Oacc[f][1] * inv0);
        *(float2*)&ctx_out[i8] = make_float2(Oacc[f][2] * inv1, Oacc[f][3] * inv1);
    }
}

extern "C" void kernel_launch(void* const* d_in, const int* in_sizes, int n_in,
                              void* d_out, int out_size) {
    const float* X    = (const float*)d_in[0];
    const float* mask = (const float*)d_in[1];
    const float* res  = (const float*)d_in[2];
    const float* Wq   = (const float*)d_in[3];
    const float* bq   = (const float*)d_in[4];
    const float* Wk   = (const float*)d_in[5];
    const float* bk   = (const float*)d_in[6];
    const float* Wv   = (const float*)d_in[7];
    const float* bv   = (const float*)d_in[8];

    float* ctx     = (float*)d_out;
    float* res_out = (float*)d_out + (size_t)NB * SQ * DM;

    dim3 g1(DM / 64, (NB * SQ) / 128, 3);
    qkv_kernel<<<g1, 256>>>(X, Wq, bq, Wk, bk, Wv, bv);

    dim3 g2(SQ / 64, NH, NB);
    attn_kernel<<<g2, 128>>>(res, mask, ctx, res_out);
}